// round 14
// baseline (speedup 1.0000x reference)
#include <cuda_runtime.h>
#include <cuda_fp16.h>
#include <math.h>
#include <stdint.h>

#define NR  8192
#define DIM 512
#define TM  128
#define TN  256
#define KC  64
#define NCHUNK (DIM / KC)            // 8 (even -> slot parity = kc&1 every tile)
#define NTHREADS 256
#define GRID_P 296                   // 2 persistent CTAs per SM
#define NTN (NR / TN)                // 32
#define NTILES ((NR / TM) * NTN)     // 2048
#define STAGE_BYTES 49152            // A 16KB + B 32KB
#define SMEM_RED (2 * STAGE_BYTES)   // 98304
#define SMEM_TOTAL (SMEM_RED + 384 * 8)

// ---------------- device scratch (allocation-free rule) ----------------
__device__ __half             g_xh[NR * DIM];
__device__ __half             g_yh[NR * DIM];
__device__ float              g_nrm[2 * NR];
__device__ unsigned long long g_rbest[NR];     // (f2o(val)<<32) | argmax col
__device__ unsigned long long g_cbest[NR];     // (f2o(val)<<32) | argmax row

__device__ __forceinline__ unsigned f2o(float f) {
    unsigned b = __float_as_uint(f);
    return (b & 0x80000000u) ? ~b : (b | 0x80000000u);
}
__device__ __forceinline__ unsigned long long umax64(unsigned long long a,
                                                     unsigned long long b) {
    return a > b ? a : b;
}

// ---------------- PTX helpers (sm_80-era, valid on sm_100 base) ----------------
__device__ __forceinline__ uint32_t smem_u32(const void* p) {
    uint32_t a;
    asm("{ .reg .u64 t; cvta.to.shared.u64 t, %1; cvt.u32.u64 %0, t; }" : "=r"(a) : "l"(p));
    return a;
}
__device__ __forceinline__ void cp16(uint32_t dst, const void* src) {
    asm volatile("cp.async.cg.shared.global [%0], [%1], 16;" :: "r"(dst), "l"(src));
}
__device__ __forceinline__ void cp_commit() { asm volatile("cp.async.commit_group;"); }
template <int N> __device__ __forceinline__ void cp_wait() {
    asm volatile("cp.async.wait_group %0;" :: "n"(N));
}
__device__ __forceinline__ void ldsm4(uint32_t& r0, uint32_t& r1, uint32_t& r2,
                                      uint32_t& r3, uint32_t addr) {
    asm volatile("ldmatrix.sync.aligned.m8n8.x4.shared.b16 {%0,%1,%2,%3}, [%4];"
                 : "=r"(r0), "=r"(r1), "=r"(r2), "=r"(r3) : "r"(addr));
}
__device__ __forceinline__ void mma16816_f16(uint32_t* c, const uint32_t* a,
                                             const uint32_t* b) {
    asm volatile(
        "mma.sync.aligned.m16n8k16.row.col.f16.f16.f16.f16 "
        "{%0,%1}, {%2,%3,%4,%5}, {%6,%7}, {%0,%1};"
        : "+r"(c[0]), "+r"(c[1])
        : "r"(a[0]), "r"(a[1]), "r"(a[2]), "r"(a[3]), "r"(b[0]), "r"(b[1]));
}

// ---------------- kernels ----------------
__global__ void init_kernel(float* out, int out_size) {
    int i = blockIdx.x * blockDim.x + threadIdx.x;
    if (i < NR) { g_rbest[i] = 0ull; g_cbest[i] = 0ull; }
    if (i < out_size) out[i] = 0.f;
}

__global__ void dummy_kernel() {}   // keeps gemm at ncu capture index 5

__global__ void normalize_kernel(const float* __restrict__ ex,
                                 const float* __restrict__ ey) {
    const float* src = blockIdx.y ? ey : ex;
    __half*      dh  = blockIdx.y ? g_yh : g_xh;
    int row = blockIdx.x, t = threadIdx.x;
    float4 v = ((const float4*)(src + (size_t)row * DIM))[t];
    float ss = v.x * v.x + v.y * v.y + v.z * v.z + v.w * v.w;
#pragma unroll
    for (int off = 16; off; off >>= 1) ss += __shfl_xor_sync(0xffffffffu, ss, off);
    __shared__ float sred[4];
    if ((t & 31) == 0) sred[t >> 5] = ss;
    __syncthreads();
    float nrm = fmaxf(sqrtf(sred[0] + sred[1] + sred[2] + sred[3]), 1e-8f);
    if (t == 0) g_nrm[blockIdx.y * NR + row] = nrm;
    float inv = 1.0f / nrm;
    __half2 p0 = __floats2half2_rn(v.x * inv, v.y * inv);
    __half2 p1 = __floats2half2_rn(v.z * inv, v.w * inv);
    ((__half2*)(dh + (size_t)row * DIM))[t * 2]     = p0;
    ((__half2*)(dh + (size_t)row * DIM))[t * 2 + 1] = p1;
}

// load one K-chunk (64 f16 = 128B rows, SW128 swizzle): A 128 rows + B 256 rows
__device__ __forceinline__ void load_chunk(int chunk, int slot, int cm, int cn,
                                           uint32_t sbase) {
    const int k0 = chunk * KC;
    const uint32_t s0 = sbase + slot * STAGE_BYTES;
    const int tid = threadIdx.x;
#pragma unroll
    for (int i = 0; i < 4; i++) {
        int c = tid + i * NTHREADS;
        int row = c >> 3, seg = c & 7;
        uint32_t off = row * 128 + seg * 16;
        off ^= ((off >> 3) & 0x70);
        cp16(s0 + off, g_xh + (size_t)(cm + row) * DIM + k0 + seg * 8);
    }
#pragma unroll
    for (int i = 0; i < 8; i++) {
        int c = tid + i * NTHREADS;
        int row = c >> 3, seg = c & 7;
        uint32_t off = row * 128 + seg * 16;
        off ^= ((off >> 3) & 0x70);
        cp16(s0 + 16384 + off, g_yh + (size_t)(cn + row) * DIM + k0 + seg * 8);
    }
}

// Persistent (clean): 296 CTAs x ~7 tiles. Slot parity = kc&1 (compile-time,
// NCHUNK even). kc loop fully unrolled; only cm/cn are runtime per tile.
// 8 warps (2x4) of 64x64, f16 accum, 2 CTAs/SM, collapsed addressing, ks rot.
__global__ __launch_bounds__(NTHREADS, 2) void gemm_max_kernel() {
    extern __shared__ char smem[];
    const uint32_t sbase = smem_u32(smem);
    const int tid = threadIdx.x, wid = tid >> 5, lane = tid & 31;
    const int wm = wid >> 2, wn = wid & 3;
    unsigned long long* sRow = (unsigned long long*)(smem + SMEM_RED);  // 128
    unsigned long long* sCol = sRow + 128;                              // 256

    for (int i = tid; i < 384; i += NTHREADS) sRow[i] = 0ull;

    const int g = lane >> 3;
    const int a_row = wm * 64 + (lane & 7) + (g & 1) * 8;
    const int b_row = wn * 64 + (lane & 7) + (g >> 1) * 8;
    const uint32_t msk = (lane & 7) << 4;
    const uint32_t ka0 = (uint32_t)((g >> 1) * 16);
    const uint32_t kb0 = (uint32_t)((g & 1) * 16);
    uint32_t aRB[4], bRB[4];
#pragma unroll
    for (int mi = 0; mi < 4; mi++) aRB[mi] = (a_row + mi * 16) * 128;
#pragma unroll
    for (int nq = 0; nq < 4; nq++) bRB[nq] = 16384 + (b_row + nq * 16) * 128;
    const int ks_rot = wid & 3;

    __syncthreads();                      // sRow/sCol zeroed before first epilogue

    // prologue: chunk 0 of first tile -> slot 0
    {
        int t0 = blockIdx.x;
        load_chunk(0, 0, (t0 >> 5) * TM, (t0 & 31) * TN, sbase);
        cp_commit();
    }

#pragma unroll 1
    for (int tile = blockIdx.x; tile < NTILES; tile += GRID_P) {
        const int cm = (tile >> 5) * TM, cn = (tile & 31) * TN;
        const int ntile = tile + GRID_P;
        const int ncm = (ntile >> 5) * TM, ncn = (ntile & 31) * TN;
        const bool have_next = (ntile < NTILES);

        uint32_t acc[4][8][2];
#pragma unroll
        for (int mi = 0; mi < 4; mi++)
#pragma unroll
            for (int nj = 0; nj < 8; nj++)
                { acc[mi][nj][0] = 0u; acc[mi][nj][1] = 0u; }

#pragma unroll
        for (int kc = 0; kc < NCHUNK; kc++) {
            cp_wait<0>();
            __syncthreads();
            if (kc + 1 < NCHUNK) {
                load_chunk(kc + 1, (kc + 1) & 1, cm, cn, sbase);   // compile-time slot
            } else if (have_next) {
                load_chunk(0, 0, ncm, ncn, sbase);                 // next tile chunk 0
            }
            cp_commit();

            const uint32_t S = sbase + (kc & 1) * STAGE_BYTES;     // compile-time
#pragma unroll
            for (int ksi = 0; ksi < 4; ksi++) {
                const int ks = (ksi + ks_rot) & 3;
                const uint32_t kxa = ((uint32_t)(ks * 32) + ka0) ^ msk;
                const uint32_t kxb = ((uint32_t)(ks * 32) + kb0) ^ msk;
                uint32_t a[4][4];
#pragma unroll
                for (int mi = 0; mi < 4; mi++)
                    ldsm4(a[mi][0], a[mi][1], a[mi][2], a[mi][3], S + aRB[mi] + kxa);
                uint32_t b[8][2];
#pragma unroll
                for (int nq = 0; nq < 4; nq++)
                    ldsm4(b[nq * 2][0], b[nq * 2][1], b[nq * 2 + 1][0],
                          b[nq * 2 + 1][1], S + bRB[nq] + kxb);
#pragma unroll
                for (int mi = 0; mi < 4; mi++)
#pragma unroll
                    for (int nj = 0; nj < 8; nj++)
                        mma16816_f16(acc[mi][nj], a[mi], b[nj]);
            }
        }

        // -------- per-tile epilogue: row/col argmax --------
#pragma unroll
        for (int mi = 0; mi < 4; mi++)
#pragma unroll
            for (int h = 0; h < 2; h++) {
                unsigned long long best = 0ull;
#pragma unroll
                for (int nj = 0; nj < 8; nj++) {
                    __half2 hv = *reinterpret_cast<__half2*>(&acc[mi][nj][h]);
                    float f0 = __low2float(hv), f1 = __high2float(hv);
                    unsigned colb = cn + wn * 64 + nj * 8 + (lane & 3) * 2;
                    best = umax64(best, ((unsigned long long)f2o(f0) << 32) | colb);
                    best = umax64(best, ((unsigned long long)f2o(f1) << 32) | (colb + 1));
                }
                best = umax64(best, __shfl_xor_sync(0xffffffffu, best, 1));
                best = umax64(best, __shfl_xor_sync(0xffffffffu, best, 2));
                if ((lane & 3) == 0)
                    atomicMax(&sRow[wm * 64 + mi * 16 + h * 8 + (lane >> 2)], best);
            }
#pragma unroll
        for (int nj = 0; nj < 8; nj++)
#pragma unroll
            for (int p = 0; p < 2; p++) {
                unsigned long long best = 0ull;
#pragma unroll
                for (int mi = 0; mi < 4; mi++)
#pragma unroll
                    for (int h = 0; h < 2; h++) {
                        __half2 hv = *reinterpret_cast<__half2*>(&acc[mi][nj][h]);
                        float v = p ? __high2float(hv) : __low2float(hv);
                        unsigned row = cm + wm * 64 + mi * 16 + h * 8 + (lane >> 2);
                        best = umax64(best, ((unsigned long long)f2o(v) << 32) | row);
                    }
                best = umax64(best, __shfl_xor_sync(0xffffffffu, best, 4));
                best = umax64(best, __shfl_xor_sync(0xffffffffu, best, 8));
                best = umax64(best, __shfl_xor_sync(0xffffffffu, best, 16));
                if (lane < 4)
                    atomicMax(&sCol[wn * 64 + nj * 8 + (lane & 3) * 2 + p], best);
            }
        __syncthreads();
        if (tid < 128) atomicMax(&g_rbest[cm + tid], sRow[tid]);
        atomicMax(&g_cbest[cn + tid], sCol[tid]);
        __syncthreads();
        for (int i = tid; i < 384; i += NTHREADS) sRow[i] = 0ull;
        // next chunk-boundary __syncthreads orders this zeroing before the
        // next epilogue's shared atomics
    }
}

// one warp per (row|col): exact fp32 dot of raw inputs / norms, then entropy term.
__global__ void refine_entropy_kernel(const float* __restrict__ ex,
                                      const float* __restrict__ ey,
                                      float* __restrict__ out) {
    int w    = (blockIdx.x * blockDim.x + threadIdx.x) >> 5;
    int lane = threadIdx.x & 31;
    int wlocal = (threadIdx.x >> 5);
    int side = (w >= NR);
    const float *va, *vb;
    float nx, ny;
    if (!side) {
        unsigned m = (unsigned)g_rbest[w];
        va = ex + (size_t)w * DIM;  vb = ey + (size_t)m * DIM;
        nx = g_nrm[w];              ny = g_nrm[NR + m];
    } else {
        int c = w - NR;
        unsigned m = (unsigned)g_cbest[c];
        va = ex + (size_t)m * DIM;  vb = ey + (size_t)c * DIM;
        nx = g_nrm[m];              ny = g_nrm[NR + c];
    }
    float s = 0.f;
#pragma unroll
    for (int i = 0; i < 4; i++) {
        int e = (i * 32 + lane) * 4;
        float4 a = *(const float4*)(va + e);
        float4 b = *(const float4*)(vb + e);
        s += a.x * b.x + a.y * b.y + a.z * b.z + a.w * b.w;
    }
#pragma unroll
    for (int off = 16; off; off >>= 1) s += __shfl_xor_sync(0xffffffffu, s, off);

    __shared__ float sacc[8];
    if (lane == 0) {
        float x  = s / (nx * ny);
        float z  = (x - 1.0f) * (1.0f / 0.3f);
        float lp = fmaf(-0.5f, z * z, 0.28503427112126339f);  // -log(.3)-.5log(2pi)
        sacc[wlocal] = -expf(lp) * lp;
    }
    __syncthreads();
    if (threadIdx.x == 0) {
        float t = 0.f;
#pragma unroll
        for (int i = 0; i < 8; i++) t += sacc[i];
        atomicAdd(&out[side], t);
    }
}

extern "C" void kernel_launch(void* const* d_in, const int* in_sizes, int n_in,
                              void* d_out, int out_size) {
    const float* ex = (const float*)d_in[0];
    const float* ey = (const float*)d_in[1];
    float* out = (float*)d_out;

    cudaFuncSetAttribute(gemm_max_kernel, cudaFuncAttributeMaxDynamicSharedMemorySize,
                         SMEM_TOTAL);

    init_kernel<<<(NR + 255) / 256, 256>>>(out, out_size);
    normalize_kernel<<<dim3(NR, 2), 128>>>(ex, ey);
    dummy_kernel<<<1, 32>>>();   // aligns gemm with ncu capture index 5
    gemm_max_kernel<<<GRID_P, NTHREADS, SMEM_TOTAL>>>();
    refine_entropy_kernel<<<(2 * NR) / 8, 256>>>(ex, ey, out);
}

// round 15
// speedup vs baseline: 1.0914x; 1.0914x over previous
#include <cuda_runtime.h>
#include <cuda_fp16.h>
#include <math.h>
#include <stdint.h>

#define NR  8192
#define DIM 512
#define TM  128
#define TN  256
#define KC  64
#define NCHUNK (DIM / KC)            // 8
#define NTHREADS 256
#define STAGE_BYTES 49152            // A 16KB + B 32KB
#define NSTAGE 2
#define SMEM_RED (NSTAGE * STAGE_BYTES)      // 98304
#define SMEM_TOTAL (SMEM_RED + 384 * 8)      // + sRow(128)+sCol(256) u64

// ---------------- device scratch (allocation-free rule) ----------------
__device__ __half             g_xh[NR * DIM];
__device__ __half             g_yh[NR * DIM];
__device__ float              g_nrm[2 * NR];
__device__ unsigned long long g_rbest[NR];     // (f2o(val)<<32) | argmax col
__device__ unsigned long long g_cbest[NR];     // (f2o(val)<<32) | argmax row

__device__ __forceinline__ unsigned f2o(float f) {
    unsigned b = __float_as_uint(f);
    return (b & 0x80000000u) ? ~b : (b | 0x80000000u);
}
__device__ __forceinline__ unsigned long long umax64(unsigned long long a,
                                                     unsigned long long b) {
    return a > b ? a : b;
}

// ---------------- PTX helpers (sm_80-era, valid on sm_100 base) ----------------
__device__ __forceinline__ uint32_t smem_u32(const void* p) {
    uint32_t a;
    asm("{ .reg .u64 t; cvta.to.shared.u64 t, %1; cvt.u32.u64 %0, t; }" : "=r"(a) : "l"(p));
    return a;
}
__device__ __forceinline__ void cp16(uint32_t dst, const void* src) {
    asm volatile("cp.async.cg.shared.global [%0], [%1], 16;" :: "r"(dst), "l"(src));
}
__device__ __forceinline__ void cp_commit() { asm volatile("cp.async.commit_group;"); }
template <int N> __device__ __forceinline__ void cp_wait() {
    asm volatile("cp.async.wait_group %0;" :: "n"(N));
}
__device__ __forceinline__ void ldsm4(uint32_t& r0, uint32_t& r1, uint32_t& r2,
                                      uint32_t& r3, uint32_t addr) {
    asm volatile("ldmatrix.sync.aligned.m8n8.x4.shared.b16 {%0,%1,%2,%3}, [%4];"
                 : "=r"(r0), "=r"(r1), "=r"(r2), "=r"(r3) : "r"(addr));
}
// f16 inputs, f16 accumulators: 2-reg C fragment
__device__ __forceinline__ void mma16816_f16(uint32_t* c, const uint32_t* a,
                                             const uint32_t* b) {
    asm volatile(
        "mma.sync.aligned.m16n8k16.row.col.f16.f16.f16.f16 "
        "{%0,%1}, {%2,%3,%4,%5}, {%6,%7}, {%0,%1};"
        : "+r"(c[0]), "+r"(c[1])
        : "r"(a[0]), "r"(a[1]), "r"(a[2]), "r"(a[3]), "r"(b[0]), "r"(b[1]));
}

// ---------------- kernels ----------------
__global__ void init_kernel(float* out, int out_size) {
    int i = blockIdx.x * blockDim.x + threadIdx.x;
    if (i < NR) { g_rbest[i] = 0ull; g_cbest[i] = 0ull; }
    if (i < out_size) out[i] = 0.f;
}

__global__ void dummy_kernel() {}   // keeps gemm at ncu capture index 5

// one 128-thread block per row; y: 0 -> ex, 1 -> ey. f16 normalized + norm.
__global__ void normalize_kernel(const float* __restrict__ ex,
                                 const float* __restrict__ ey) {
    const float* src = blockIdx.y ? ey : ex;
    __half*      dh  = blockIdx.y ? g_yh : g_xh;
    int row = blockIdx.x, t = threadIdx.x;
    float4 v = ((const float4*)(src + (size_t)row * DIM))[t];
    float ss = v.x * v.x + v.y * v.y + v.z * v.z + v.w * v.w;
#pragma unroll
    for (int off = 16; off; off >>= 1) ss += __shfl_xor_sync(0xffffffffu, ss, off);
    __shared__ float sred[4];
    if ((t & 31) == 0) sred[t >> 5] = ss;
    __syncthreads();
    float nrm = fmaxf(sqrtf(sred[0] + sred[1] + sred[2] + sred[3]), 1e-8f);
    if (t == 0) g_nrm[blockIdx.y * NR + row] = nrm;
    float inv = 1.0f / nrm;
    __half2 p0 = __floats2half2_rn(v.x * inv, v.y * inv);
    __half2 p1 = __floats2half2_rn(v.z * inv, v.w * inv);
    ((__half2*)(dh + (size_t)row * DIM))[t * 2]     = p0;
    ((__half2*)(dh + (size_t)row * DIM))[t * 2 + 1] = p1;
}

// load one K-chunk (64 f16 = 128B rows, SW128 swizzle): A 128 rows + B 256 rows
__device__ __forceinline__ void load_chunk(int chunk, int slot, int cm, int cn,
                                           uint32_t sbase) {
    const int k0 = chunk * KC;
    const uint32_t s0 = sbase + slot * STAGE_BYTES;
    const int tid = threadIdx.x;
#pragma unroll
    for (int i = 0; i < 4; i++) {        // A: 1024 segs (128 rows x 8)
        int c = tid + i * NTHREADS;
        int row = c >> 3, seg = c & 7;
        uint32_t off = row * 128 + seg * 16;
        off ^= ((off >> 3) & 0x70);
        cp16(s0 + off, g_xh + (size_t)(cm + row) * DIM + k0 + seg * 8);
    }
#pragma unroll
    for (int i = 0; i < 8; i++) {        // B: 2048 segs (256 rows x 8)
        int c = tid + i * NTHREADS;
        int row = c >> 3, seg = c & 7;
        uint32_t off = row * 128 + seg * 16;
        off ^= ((off >> 3) & 0x70);
        cp16(s0 + 16384 + off, g_yh + (size_t)(cn + row) * DIM + k0 + seg * 8);
    }
}

// 8 warps (2x4), warp tile 64x64, f16 accum, 2 CTAs/SM, 2-stage pipeline.
// ks rotation chosen so all 4 warps per SMSP (2 per CTA x 2 CTAs) are in
// DISTINCT phases: SMSP = wid%4; same-SMSP warps of one CTA differ in wid>>2,
// co-resident CTAs differ in blockIdx parity.
__global__ __launch_bounds__(NTHREADS, 2) void gemm_max_kernel() {
    extern __shared__ char smem[];
    const uint32_t sbase = smem_u32(smem);
    const int tid = threadIdx.x, wid = tid >> 5, lane = tid & 31;
    const int wm = wid >> 2, wn = wid & 3;           // 2x4 warps, warp tile 64x64
    const int cm = blockIdx.y * TM, cn = blockIdx.x * TN;
    unsigned long long* sRow = (unsigned long long*)(smem + SMEM_RED);  // 128
    unsigned long long* sCol = sRow + 128;                              // 256

    for (int i = tid; i < 384; i += NTHREADS) sRow[i] = 0ull;

    uint32_t acc[4][8][2];     // f16x2 accumulators: 64 regs
#pragma unroll
    for (int mi = 0; mi < 4; mi++)
#pragma unroll
        for (int nj = 0; nj < 8; nj++)
            { acc[mi][nj][0] = 0u; acc[mi][nj][1] = 0u; }

    // ldmatrix addressing (group-of-8 pattern), swizzle-collapsed form
    const int g = lane >> 3;
    const int a_row = wm * 64 + (lane & 7) + (g & 1) * 8;   // + mi*16
    const int b_row = wn * 64 + (lane & 7) + (g >> 1) * 8;  // + nq*16
    const uint32_t msk = (lane & 7) << 4;                   // SW128 mask, row-only
    const uint32_t ka0 = (uint32_t)((g >> 1) * 16);         // a_sel*16
    const uint32_t kb0 = (uint32_t)((g & 1) * 16);          // b_sel*16
    uint32_t aRB[4], bRB[4];
#pragma unroll
    for (int mi = 0; mi < 4; mi++) aRB[mi] = (a_row + mi * 16) * 128;
#pragma unroll
    for (int nq = 0; nq < 4; nq++) bRB[nq] = 16384 + (b_row + nq * 16) * 128;
    // distinct phase for each of the 4 warps sharing an SMSP:
    const int ks_rot = (((wid >> 2) << 1) + (blockIdx.x & 1)) & 3;

    // prologue: chunk 0 into slot 0
    load_chunk(0, 0, cm, cn, sbase); cp_commit();

#pragma unroll
    for (int kc = 0; kc < NCHUNK; kc++) {
        cp_wait<0>();        // chunk kc resident (issued a full chunk-compute ago)
        __syncthreads();     // also: all warps done with the slot being reloaded
        if (kc + 1 < NCHUNK) { load_chunk(kc + 1, (kc + 1) & 1, cm, cn, sbase); cp_commit(); }

        const uint32_t S = sbase + (kc & 1) * STAGE_BYTES;
#pragma unroll
        for (int ksi = 0; ksi < 4; ksi++) {
            const int ks = (ksi + ks_rot) & 3;   // rotated per warp
            const uint32_t kxa = ((uint32_t)(ks * 32) + ka0) ^ msk;
            const uint32_t kxb = ((uint32_t)(ks * 32) + kb0) ^ msk;
            uint32_t a[4][4];
#pragma unroll
            for (int mi = 0; mi < 4; mi++)
                ldsm4(a[mi][0], a[mi][1], a[mi][2], a[mi][3], S + aRB[mi] + kxa);
            uint32_t b[8][2];
#pragma unroll
            for (int nq = 0; nq < 4; nq++)
                ldsm4(b[nq * 2][0], b[nq * 2][1], b[nq * 2 + 1][0], b[nq * 2 + 1][1],
                      S + bRB[nq] + kxb);
#pragma unroll
            for (int mi = 0; mi < 4; mi++)
#pragma unroll
                for (int nj = 0; nj < 8; nj++)
                    mma16816_f16(acc[mi][nj], a[mi], b[nj]);
        }
    }

    // -------- epilogue: row/col argmax from f16x2 fragments --------
#pragma unroll
    for (int mi = 0; mi < 4; mi++)
#pragma unroll
        for (int h = 0; h < 2; h++) {
            unsigned long long best = 0ull;
#pragma unroll
            for (int nj = 0; nj < 8; nj++) {
                __half2 hv = *reinterpret_cast<__half2*>(&acc[mi][nj][h]);
                float f0 = __low2float(hv), f1 = __high2float(hv);
                unsigned colb = cn + wn * 64 + nj * 8 + (lane & 3) * 2;
                best = umax64(best, ((unsigned long long)f2o(f0) << 32) | colb);
                best = umax64(best, ((unsigned long long)f2o(f1) << 32) | (colb + 1));
            }
            best = umax64(best, __shfl_xor_sync(0xffffffffu, best, 1));
            best = umax64(best, __shfl_xor_sync(0xffffffffu, best, 2));
            if ((lane & 3) == 0)
                atomicMax(&sRow[wm * 64 + mi * 16 + h * 8 + (lane >> 2)], best);
        }
#pragma unroll
    for (int nj = 0; nj < 8; nj++)
#pragma unroll
        for (int p = 0; p < 2; p++) {
            unsigned long long best = 0ull;
#pragma unroll
            for (int mi = 0; mi < 4; mi++)
#pragma unroll
                for (int h = 0; h < 2; h++) {
                    __half2 hv = *reinterpret_cast<__half2*>(&acc[mi][nj][h]);
                    float v = p ? __high2float(hv) : __low2float(hv);
                    unsigned row = cm + wm * 64 + mi * 16 + h * 8 + (lane >> 2);
                    best = umax64(best, ((unsigned long long)f2o(v) << 32) | row);
                }
            best = umax64(best, __shfl_xor_sync(0xffffffffu, best, 4));
            best = umax64(best, __shfl_xor_sync(0xffffffffu, best, 8));
            best = umax64(best, __shfl_xor_sync(0xffffffffu, best, 16));
            if (lane < 4)
                atomicMax(&sCol[wn * 64 + nj * 8 + (lane & 3) * 2 + p], best);
        }
    __syncthreads();
    if (tid < 128) atomicMax(&g_rbest[cm + tid], sRow[tid]);
    atomicMax(&g_cbest[cn + tid], sCol[tid]);
}

// one warp per (row|col): exact fp32 dot of raw inputs / norms, then entropy term.
__global__ void refine_entropy_kernel(const float* __restrict__ ex,
                                      const float* __restrict__ ey,
                                      float* __restrict__ out) {
    int w    = (blockIdx.x * blockDim.x + threadIdx.x) >> 5;
    int lane = threadIdx.x & 31;
    int wlocal = (threadIdx.x >> 5);
    int side = (w >= NR);
    const float *va, *vb;
    float nx, ny;
    if (!side) {
        unsigned m = (unsigned)g_rbest[w];
        va = ex + (size_t)w * DIM;  vb = ey + (size_t)m * DIM;
        nx = g_nrm[w];              ny = g_nrm[NR + m];
    } else {
        int c = w - NR;
        unsigned m = (unsigned)g_cbest[c];
        va = ex + (size_t)m * DIM;  vb = ey + (size_t)c * DIM;
        nx = g_nrm[m];              ny = g_nrm[NR + c];
    }
    float s = 0.f;
#pragma unroll
    for (int i = 0; i < 4; i++) {
        int e = (i * 32 + lane) * 4;
        float4 a = *(const float4*)(va + e);
        float4 b = *(const float4*)(vb + e);
        s += a.x * b.x + a.y * b.y + a.z * b.z + a.w * b.w;
    }
#pragma unroll
    for (int off = 16; off; off >>= 1) s += __shfl_xor_sync(0xffffffffu, s, off);

    __shared__ float sacc[8];
    if (lane == 0) {
        float x  = s / (nx * ny);
        float z  = (x - 1.0f) * (1.0f / 0.3f);
        float lp = fmaf(-0.5f, z * z, 0.28503427112126339f);  // -log(.3)-.5log(2pi)
        sacc[wlocal] = -expf(lp) * lp;
    }
    __syncthreads();
    if (threadIdx.x == 0) {
        float t = 0.f;
#pragma unroll
        for (int i = 0; i < 8; i++) t += sacc[i];
        atomicAdd(&out[side], t);
    }
}

extern "C" void kernel_launch(void* const* d_in, const int* in_sizes, int n_in,
                              void* d_out, int out_size) {
    const float* ex = (const float*)d_in[0];
    const float* ey = (const float*)d_in[1];
    float* out = (float*)d_out;

    cudaFuncSetAttribute(gemm_max_kernel, cudaFuncAttributeMaxDynamicSharedMemorySize,
                         SMEM_TOTAL);

    init_kernel<<<(NR + 255) / 256, 256>>>(out, out_size);
    normalize_kernel<<<dim3(NR, 2), 128>>>(ex, ey);
    dummy_kernel<<<1, 32>>>();   // aligns gemm with ncu capture index 5
    gemm_max_kernel<<<dim3(NR / TN, NR / TM), NTHREADS, SMEM_TOTAL>>>();
    refine_entropy_kernel<<<(2 * NR) / 8, 256>>>(ex, ey, out);
}

// round 16
// speedup vs baseline: 1.1052x; 1.0126x over previous
#include <cuda_runtime.h>
#include <cuda_fp16.h>
#include <math.h>
#include <stdint.h>

#define NR  8192
#define DIM 512
#define TM  128
#define TN  256
#define KC  64
#define NCHUNK (DIM / KC)            // 8
#define NTHREADS 256
#define STAGE_BYTES 49152            // A 16KB + B 32KB
#define NSTAGE 2
#define SMEM_RED (NSTAGE * STAGE_BYTES)      // 98304
#define SMEM_TOTAL (SMEM_RED + 384 * 8)      // + sRow(128)+sCol(256) u64

// ---------------- device scratch (allocation-free rule) ----------------
__device__ __half             g_xh[NR * DIM];
__device__ __half             g_yh[NR * DIM];
__device__ float              g_nrm[2 * NR];
__device__ unsigned long long g_rbest[NR];     // (f2o(val)<<32) | argmax col
__device__ unsigned long long g_cbest[NR];     // (f2o(val)<<32) | argmax row

__device__ __forceinline__ unsigned f2o(float f) {
    unsigned b = __float_as_uint(f);
    return (b & 0x80000000u) ? ~b : (b | 0x80000000u);
}
__device__ __forceinline__ unsigned long long umax64(unsigned long long a,
                                                     unsigned long long b) {
    return a > b ? a : b;
}

// ---------------- PTX helpers (sm_80-era, valid on sm_100 base) ----------------
__device__ __forceinline__ uint32_t smem_u32(const void* p) {
    uint32_t a;
    asm("{ .reg .u64 t; cvta.to.shared.u64 t, %1; cvt.u32.u64 %0, t; }" : "=r"(a) : "l"(p));
    return a;
}
__device__ __forceinline__ void cp16(uint32_t dst, const void* src) {
    asm volatile("cp.async.cg.shared.global [%0], [%1], 16;" :: "r"(dst), "l"(src));
}
__device__ __forceinline__ void cp_commit() { asm volatile("cp.async.commit_group;"); }
template <int N> __device__ __forceinline__ void cp_wait() {
    asm volatile("cp.async.wait_group %0;" :: "n"(N));
}
__device__ __forceinline__ void ldsm4(uint32_t& r0, uint32_t& r1, uint32_t& r2,
                                      uint32_t& r3, uint32_t addr) {
    asm volatile("ldmatrix.sync.aligned.m8n8.x4.shared.b16 {%0,%1,%2,%3}, [%4];"
                 : "=r"(r0), "=r"(r1), "=r"(r2), "=r"(r3) : "r"(addr));
}
// f16 inputs, f16 accumulators: 2-reg C fragment
__device__ __forceinline__ void mma16816_f16(uint32_t* c, const uint32_t* a,
                                             const uint32_t* b) {
    asm volatile(
        "mma.sync.aligned.m16n8k16.row.col.f16.f16.f16.f16 "
        "{%0,%1}, {%2,%3,%4,%5}, {%6,%7}, {%0,%1};"
        : "+r"(c[0]), "+r"(c[1])
        : "r"(a[0]), "r"(a[1]), "r"(a[2]), "r"(a[3]), "r"(b[0]), "r"(b[1]));
}

// ---------------- kernels ----------------
// one 128-thread block per row; y: 0 -> ex, 1 -> ey. f16 normalized + norm.
// Fuses init: clears g_rbest/g_cbest for this row, out[] from row 0.
__global__ void normalize_kernel(const float* __restrict__ ex,
                                 const float* __restrict__ ey,
                                 float* __restrict__ out, int out_size) {
    const float* src = blockIdx.y ? ey : ex;
    __half*      dh  = blockIdx.y ? g_yh : g_xh;
    int row = blockIdx.x, t = threadIdx.x;
    if (t == 0) {
        if (blockIdx.y == 0) g_rbest[row] = 0ull;
        else                 g_cbest[row] = 0ull;
    }
    if (row == 0 && blockIdx.y == 0 && t < out_size) out[t] = 0.f;

    float4 v = ((const float4*)(src + (size_t)row * DIM))[t];
    float ss = v.x * v.x + v.y * v.y + v.z * v.z + v.w * v.w;
#pragma unroll
    for (int off = 16; off; off >>= 1) ss += __shfl_xor_sync(0xffffffffu, ss, off);
    __shared__ float sred[4];
    if ((t & 31) == 0) sred[t >> 5] = ss;
    __syncthreads();
    float nrm = fmaxf(sqrtf(sred[0] + sred[1] + sred[2] + sred[3]), 1e-8f);
    if (t == 0) g_nrm[blockIdx.y * NR + row] = nrm;
    float inv = 1.0f / nrm;
    __half2 p0 = __floats2half2_rn(v.x * inv, v.y * inv);
    __half2 p1 = __floats2half2_rn(v.z * inv, v.w * inv);
    ((__half2*)(dh + (size_t)row * DIM))[t * 2]     = p0;
    ((__half2*)(dh + (size_t)row * DIM))[t * 2 + 1] = p1;
}

// load one K-chunk (64 f16 = 128B rows, SW128 swizzle): A 128 rows + B 256 rows
__device__ __forceinline__ void load_chunk(int chunk, int slot, int cm, int cn,
                                           uint32_t sbase) {
    const int k0 = chunk * KC;
    const uint32_t s0 = sbase + slot * STAGE_BYTES;
    const int tid = threadIdx.x;
#pragma unroll
    for (int i = 0; i < 4; i++) {        // A: 1024 segs (128 rows x 8)
        int c = tid + i * NTHREADS;
        int row = c >> 3, seg = c & 7;
        uint32_t off = row * 128 + seg * 16;
        off ^= ((off >> 3) & 0x70);
        cp16(s0 + off, g_xh + (size_t)(cm + row) * DIM + k0 + seg * 8);
    }
#pragma unroll
    for (int i = 0; i < 8; i++) {        // B: 2048 segs (256 rows x 8)
        int c = tid + i * NTHREADS;
        int row = c >> 3, seg = c & 7;
        uint32_t off = row * 128 + seg * 16;
        off ^= ((off >> 3) & 0x70);
        cp16(s0 + 16384 + off, g_yh + (size_t)(cn + row) * DIM + k0 + seg * 8);
    }
}

// 8 warps (2x4), warp tile 64x64, f16 accum, 2 CTAs/SM, 2-stage pipeline.
// (exact R12 champion mainloop: collapsed addressing, ks_rot = wid&3)
__global__ __launch_bounds__(NTHREADS, 2) void gemm_max_kernel() {
    extern __shared__ char smem[];
    const uint32_t sbase = smem_u32(smem);
    const int tid = threadIdx.x, wid = tid >> 5, lane = tid & 31;
    const int wm = wid >> 2, wn = wid & 3;           // 2x4 warps, warp tile 64x64
    const int cm = blockIdx.y * TM, cn = blockIdx.x * TN;
    unsigned long long* sRow = (unsigned long long*)(smem + SMEM_RED);  // 128
    unsigned long long* sCol = sRow + 128;                              // 256

    for (int i = tid; i < 384; i += NTHREADS) sRow[i] = 0ull;

    uint32_t acc[4][8][2];     // f16x2 accumulators: 64 regs
#pragma unroll
    for (int mi = 0; mi < 4; mi++)
#pragma unroll
        for (int nj = 0; nj < 8; nj++)
            { acc[mi][nj][0] = 0u; acc[mi][nj][1] = 0u; }

    // ldmatrix addressing (group-of-8 pattern), swizzle-collapsed form
    const int g = lane >> 3;
    const int a_row = wm * 64 + (lane & 7) + (g & 1) * 8;   // + mi*16
    const int b_row = wn * 64 + (lane & 7) + (g >> 1) * 8;  // + nq*16
    const uint32_t msk = (lane & 7) << 4;                   // SW128 mask, row-only
    const uint32_t ka0 = (uint32_t)((g >> 1) * 16);         // a_sel*16
    const uint32_t kb0 = (uint32_t)((g & 1) * 16);          // b_sel*16
    uint32_t aRB[4], bRB[4];
#pragma unroll
    for (int mi = 0; mi < 4; mi++) aRB[mi] = (a_row + mi * 16) * 128;
#pragma unroll
    for (int nq = 0; nq < 4; nq++) bRB[nq] = 16384 + (b_row + nq * 16) * 128;
    const int ks_rot = wid & 3;

    // prologue: chunk 0 into slot 0
    load_chunk(0, 0, cm, cn, sbase); cp_commit();

#pragma unroll
    for (int kc = 0; kc < NCHUNK; kc++) {
        cp_wait<0>();        // chunk kc resident (issued a full chunk-compute ago)
        __syncthreads();     // also: all warps done with the slot being reloaded
        if (kc + 1 < NCHUNK) { load_chunk(kc + 1, (kc + 1) & 1, cm, cn, sbase); cp_commit(); }

        const uint32_t S = sbase + (kc & 1) * STAGE_BYTES;
#pragma unroll
        for (int ksi = 0; ksi < 4; ksi++) {
            const int ks = (ksi + ks_rot) & 3;   // rotated per warp
            const uint32_t kxa = ((uint32_t)(ks * 32) + ka0) ^ msk;
            const uint32_t kxb = ((uint32_t)(ks * 32) + kb0) ^ msk;
            uint32_t a[4][4];
#pragma unroll
            for (int mi = 0; mi < 4; mi++)
                ldsm4(a[mi][0], a[mi][1], a[mi][2], a[mi][3], S + aRB[mi] + kxa);
            uint32_t b[8][2];
#pragma unroll
            for (int nq = 0; nq < 4; nq++)
                ldsm4(b[nq * 2][0], b[nq * 2][1], b[nq * 2 + 1][0], b[nq * 2 + 1][1],
                      S + bRB[nq] + kxb);
#pragma unroll
            for (int mi = 0; mi < 4; mi++)
#pragma unroll
                for (int nj = 0; nj < 8; nj++)
                    mma16816_f16(acc[mi][nj], a[mi], b[nj]);
        }
    }

    // -------- epilogue: row/col argmax from f16x2 fragments --------
#pragma unroll
    for (int mi = 0; mi < 4; mi++)
#pragma unroll
        for (int h = 0; h < 2; h++) {
            unsigned long long best = 0ull;
#pragma unroll
            for (int nj = 0; nj < 8; nj++) {
                __half2 hv = *reinterpret_cast<__half2*>(&acc[mi][nj][h]);
                float f0 = __low2float(hv), f1 = __high2float(hv);
                unsigned colb = cn + wn * 64 + nj * 8 + (lane & 3) * 2;
                best = umax64(best, ((unsigned long long)f2o(f0) << 32) | colb);
                best = umax64(best, ((unsigned long long)f2o(f1) << 32) | (colb + 1));
            }
            best = umax64(best, __shfl_xor_sync(0xffffffffu, best, 1));
            best = umax64(best, __shfl_xor_sync(0xffffffffu, best, 2));
            if ((lane & 3) == 0)
                atomicMax(&sRow[wm * 64 + mi * 16 + h * 8 + (lane >> 2)], best);
        }
#pragma unroll
    for (int nj = 0; nj < 8; nj++)
#pragma unroll
        for (int p = 0; p < 2; p++) {
            unsigned long long best = 0ull;
#pragma unroll
            for (int mi = 0; mi < 4; mi++)
#pragma unroll
                for (int h = 0; h < 2; h++) {
                    __half2 hv = *reinterpret_cast<__half2*>(&acc[mi][nj][h]);
                    float v = p ? __high2float(hv) : __low2float(hv);
                    unsigned row = cm + wm * 64 + mi * 16 + h * 8 + (lane >> 2);
                    best = umax64(best, ((unsigned long long)f2o(v) << 32) | row);
                }
            best = umax64(best, __shfl_xor_sync(0xffffffffu, best, 4));
            best = umax64(best, __shfl_xor_sync(0xffffffffu, best, 8));
            best = umax64(best, __shfl_xor_sync(0xffffffffu, best, 16));
            if (lane < 4)
                atomicMax(&sCol[wn * 64 + nj * 8 + (lane & 3) * 2 + p], best);
        }
    __syncthreads();
    if (tid < 128) atomicMax(&g_rbest[cm + tid], sRow[tid]);
    atomicMax(&g_cbest[cn + tid], sCol[tid]);
}

// one warp per (row|col): exact fp32 dot of raw inputs / norms, then entropy term.
__global__ void refine_entropy_kernel(const float* __restrict__ ex,
                                      const float* __restrict__ ey,
                                      float* __restrict__ out) {
    int w    = (blockIdx.x * blockDim.x + threadIdx.x) >> 5;
    int lane = threadIdx.x & 31;
    int wlocal = (threadIdx.x >> 5);
    int side = (w >= NR);
    const float *va, *vb;
    float nx, ny;
    if (!side) {
        unsigned m = (unsigned)g_rbest[w];
        va = ex + (size_t)w * DIM;  vb = ey + (size_t)m * DIM;
        nx = g_nrm[w];              ny = g_nrm[NR + m];
    } else {
        int c = w - NR;
        unsigned m = (unsigned)g_cbest[c];
        va = ex + (size_t)m * DIM;  vb = ey + (size_t)c * DIM;
        nx = g_nrm[m];              ny = g_nrm[NR + c];
    }
    float s = 0.f;
#pragma unroll
    for (int i = 0; i < 4; i++) {
        int e = (i * 32 + lane) * 4;
        float4 a = *(const float4*)(va + e);
        float4 b = *(const float4*)(vb + e);
        s += a.x * b.x + a.y * b.y + a.z * b.z + a.w * b.w;
    }
#pragma unroll
    for (int off = 16; off; off >>= 1) s += __shfl_xor_sync(0xffffffffu, s, off);

    __shared__ float sacc[8];
    if (lane == 0) {
        float x  = s / (nx * ny);
        float z  = (x - 1.0f) * (1.0f / 0.3f);
        float lp = fmaf(-0.5f, z * z, 0.28503427112126339f);  // -log(.3)-.5log(2pi)
        sacc[wlocal] = -expf(lp) * lp;
    }
    __syncthreads();
    if (threadIdx.x == 0) {
        float t = 0.f;
#pragma unroll
        for (int i = 0; i < 8; i++) t += sacc[i];
        atomicAdd(&out[side], t);
    }
}

extern "C" void kernel_launch(void* const* d_in, const int* in_sizes, int n_in,
                              void* d_out, int out_size) {
    const float* ex = (const float*)d_in[0];
    const float* ey = (const float*)d_in[1];
    float* out = (float*)d_out;

    cudaFuncSetAttribute(gemm_max_kernel, cudaFuncAttributeMaxDynamicSharedMemorySize,
                         SMEM_TOTAL);

    normalize_kernel<<<dim3(NR, 2), 128>>>(ex, ey, out, out_size);
    gemm_max_kernel<<<dim3(NR / TN, NR / TM), NTHREADS, SMEM_TOTAL>>>();
    refine_entropy_kernel<<<(2 * NR) / 8, 256>>>(ex, ey, out);
}